// round 1
// baseline (speedup 1.0000x reference)
#include <cuda_runtime.h>
#include <cstdint>

#define Bn 256
#define Tn 512
#define Hn 256
#define G3 768
#define NBLK 128   // recurrent blocks; block j owns h-columns 2j, 2j+1

// ---------------- scratch (device globals: no allocation allowed) ----------
__device__ float g_Gi[(size_t)Tn * G3 * Bn];   // [t][g][b], g = gate*256 + c
__device__ float g_h[2 * Hn * Bn];             // ping-pong, [p][c][b]
__device__ unsigned char g_rst[Tn * Bn];       // [t][b], normalized 0/1
__device__ volatile unsigned g_gen;
__device__ unsigned g_cnt;

// ---------------- grid barrier (128 co-resident blocks) --------------------
__device__ __forceinline__ void gridbar(unsigned target) {
    __syncthreads();
    if (threadIdx.x == 0) {
        __threadfence();
        unsigned a = atomicAdd(&g_cnt, 1u);
        if (a == (unsigned)gridDim.x - 1u) {
            g_cnt = 0;
            __threadfence();
            atomicAdd((unsigned*)&g_gen, 1u);
        } else {
            while (g_gen < target) { __nanosleep(64); }
        }
        __threadfence();
    }
    __syncthreads();
}

// ---------------- init: reset barrier, init h (transposed), transpose resets
// resets dtype is ambiguous (bool/int8 vs int32). Detect by byte pattern:
// int32 0/1 little-endian has zero bytes at offsets i%4 != 0.
__global__ void init_kernel(const float* __restrict__ h0,
                            const unsigned char* __restrict__ resets) {
    int i = blockIdx.x * blockDim.x + threadIdx.x;
    if (i == 0) { g_gen = 0; g_cnt = 0; }

    // detect dtype of resets from first 256 bytes (safe either way: >=512KB int32
    // or >=128KB uint8 buffer)
    bool is_u8 = false;
    #pragma unroll 4
    for (int j = 0; j < 64; j++) {
        if (resets[j * 4 + 1] | resets[j * 4 + 2] | resets[j * 4 + 3]) is_u8 = true;
    }

    if (i < Hn * Bn) {
        int c = i / Bn, b = i % Bn;
        g_h[c * Bn + b] = h0[b * Hn + c];   // [c][b] <- [b][c]
    }
    if (i < Tn * Bn) {
        int t = i / Bn, b = i % Bn;
        int src = b * Tn + t;
        unsigned char v;
        if (is_u8) v = resets[src] ? 1 : 0;
        else       v = reinterpret_cast<const int*>(resets)[src] ? 1 : 0;
        g_rst[i] = v;
    }
}

// ---------------- Gi = x @ Wi + bi, stored [t][g][b] ------------------------
// grid: (B/64, 3H/64, T), 256 threads, 4x4 micro-tile per thread.
__global__ void __launch_bounds__(256) gi_gemm(const float* __restrict__ x,
                                               const float* __restrict__ Wi,
                                               const float* __restrict__ bi) {
    int t  = blockIdx.z;
    int g0 = blockIdx.y * 64;
    int b0 = blockIdx.x * 64;

    __shared__ float As[16][64];   // Wi[k][g] chunk
    __shared__ float Bs[16][64];   // x  [k][b] chunk (transposed on store)

    int tid = threadIdx.x;
    int tx = tid & 15;             // -> b (4 consecutive)
    int ty = tid >> 4;             // -> g (4 consecutive)

    float acc[4][4];
    #pragma unroll
    for (int i = 0; i < 4; i++)
        #pragma unroll
        for (int j = 0; j < 4; j++) acc[i][j] = 0.f;

    for (int k0 = 0; k0 < Hn; k0 += 16) {
        // load As: 16x64, 4 rows per thread-group, coalesced over g
        {
            int gg = tid & 63;
            int kk = tid >> 6;     // 0..3
            #pragma unroll
            for (int r = 0; r < 4; r++)
                As[kk + 4 * r][gg] = Wi[(size_t)(k0 + kk + 4 * r) * G3 + g0 + gg];
        }
        // load Bs: x[b][t][k] -> Bs[k][b]; float4 over k per thread
        {
            int bb = tid >> 2;           // 0..63
            int k4 = (tid & 3) * 4;
            const float4 v = *reinterpret_cast<const float4*>(
                &x[((size_t)(b0 + bb) * Tn + t) * Hn + k0 + k4]);
            Bs[k4 + 0][bb] = v.x;
            Bs[k4 + 1][bb] = v.y;
            Bs[k4 + 2][bb] = v.z;
            Bs[k4 + 3][bb] = v.w;
        }
        __syncthreads();

        #pragma unroll
        for (int kk = 0; kk < 16; kk++) {
            float4 a4 = *reinterpret_cast<const float4*>(&As[kk][ty * 4]);
            float4 b4 = *reinterpret_cast<const float4*>(&Bs[kk][tx * 4]);
            float a[4] = {a4.x, a4.y, a4.z, a4.w};
            float bv[4] = {b4.x, b4.y, b4.z, b4.w};
            #pragma unroll
            for (int i = 0; i < 4; i++)
                #pragma unroll
                for (int j = 0; j < 4; j++) acc[i][j] += a[i] * bv[j];
        }
        __syncthreads();
    }

    #pragma unroll
    for (int i = 0; i < 4; i++) {
        int g = g0 + ty * 4 + i;
        float bv = bi[g];
        float4 o = make_float4(acc[i][0] + bv, acc[i][1] + bv,
                               acc[i][2] + bv, acc[i][3] + bv);
        *reinterpret_cast<float4*>(&g_Gi[((size_t)t * G3 + g) * Bn + b0 + tx * 4]) = o;
    }
}

// ---------------- recurrent scan: persistent, 1 barrier/step ----------------
__device__ __forceinline__ float sigmoidf_(float v) {
    return __fdividef(1.f, 1.f + __expf(-v));
}

__global__ void __launch_bounds__(256, 1) rnn_kernel(const float* __restrict__ Wh,
                                                     const float* __restrict__ bn,
                                                     float* __restrict__ out) {
    // Wh columns for this block, packed 8 floats per k: {r0,z0,n0,r1,z1,n1,0,0}
    __shared__ float4 ws[Hn * 2];

    const int b  = threadIdx.x;        // batch row owned by this thread
    const int c0 = blockIdx.x * 2;
    const int c1 = c0 + 1;

    for (int k = threadIdx.x; k < Hn; k += blockDim.x) {
        const float* w = Wh + (size_t)k * G3;
        ws[k * 2 + 0] = make_float4(w[c0], w[256 + c0], w[512 + c0], w[c1]);
        ws[k * 2 + 1] = make_float4(w[256 + c1], w[512 + c1], 0.f, 0.f);
    }
    const float bn0 = bn[c0];
    const float bn1 = bn[c1];
    __syncthreads();

    float* outy = out + Hn * Bn;       // ys region after hT

    for (int t = 0; t < Tn; t++) {
        const int p = t & 1;
        const float* hin  = g_h + p * (Hn * Bn);
        float*       hout = g_h + (p ^ 1) * (Hn * Bn);

        float a0 = 0.f, a1 = 0.f, a2 = 0.f, a3 = 0.f, a4 = 0.f, a5 = 0.f;
        #pragma unroll 8
        for (int k = 0; k < Hn; k++) {
            float  hv = __ldcg(&hin[k * Bn + b]);
            float4 w0 = ws[k * 2 + 0];
            float4 w1 = ws[k * 2 + 1];
            a0 += hv * w0.x; a1 += hv * w0.y; a2 += hv * w0.z;
            a3 += hv * w0.w; a4 += hv * w1.x; a5 += hv * w1.y;
        }

        const float m = g_rst[t * Bn + b] ? 0.f : 1.f;    // reset BEFORE cell
        const float h0v = __ldcg(&hin[c0 * Bn + b]) * m;
        const float h1v = __ldcg(&hin[c1 * Bn + b]) * m;

        const float* gi = g_Gi + (size_t)t * G3 * Bn;
        float r0 = sigmoidf_(__ldcs(&gi[(      c0) * Bn + b]) + a0 * m);
        float z0 = sigmoidf_(__ldcs(&gi[(256 + c0) * Bn + b]) + a1 * m);
        float n0 = tanhf    (__ldcs(&gi[(512 + c0) * Bn + b]) + r0 * (a2 * m + bn0));
        float r1 = sigmoidf_(__ldcs(&gi[(      c1) * Bn + b]) + a3 * m);
        float z1 = sigmoidf_(__ldcs(&gi[(256 + c1) * Bn + b]) + a4 * m);
        float n1 = tanhf    (__ldcs(&gi[(512 + c1) * Bn + b]) + r1 * (a5 * m + bn1));

        float nh0 = (1.f - z0) * n0 + z0 * h0v;
        float nh1 = (1.f - z1) * n1 + z1 * h1v;

        hout[c0 * Bn + b] = nh0;
        hout[c1 * Bn + b] = nh1;

        *reinterpret_cast<float2*>(&outy[((size_t)b * Tn + t) * Hn + c0]) =
            make_float2(nh0, nh1);
        if (t == Tn - 1) {
            *reinterpret_cast<float2*>(&out[b * Hn + c0]) = make_float2(nh0, nh1);
        }

        if (t < Tn - 1) gridbar((unsigned)(t + 1));
    }
}

// ---------------- launch ----------------------------------------------------
extern "C" void kernel_launch(void* const* d_in, const int* in_sizes, int n_in,
                              void* d_out, int out_size) {
    const float*         x      = (const float*)d_in[0];
    const unsigned char* resets = (const unsigned char*)d_in[1];
    const float*         Wi     = (const float*)d_in[2];
    const float*         bi     = (const float*)d_in[3];
    const float*         Wh     = (const float*)d_in[4];
    const float*         bn     = (const float*)d_in[5];
    const float*         h0     = (const float*)d_in[6];
    float* out = (float*)d_out;

    init_kernel<<<(Tn * Bn + 255) / 256, 256>>>(h0, resets);

    dim3 g(Bn / 64, G3 / 64, Tn);
    gi_gemm<<<g, 256>>>(x, Wi, bi);

    rnn_kernel<<<NBLK, 256>>>(Wh, bn, out);
}

// round 4
// speedup vs baseline: 1.6619x; 1.6619x over previous
#include <cuda_runtime.h>
#include <cstdint>

#define Bn 256
#define Tn 512
#define Hn 256
#define G3 768

#define NBG 8          // batch groups (32 rows each)
#define NCG 16         // column groups (16 h-cols each)
#define RNN_BLOCKS (NBG * NCG)      // 128
#define RNN_THREADS 128
#define HS_LD 40       // padded hs row stride (floats), 160B: 16B-aligned, conflict-free

// ---------------- scratch (device globals: no allocation allowed) ----------
__device__ float g_Gi[(size_t)Tn * G3 * Bn];   // [t][g][b], g = gate*256 + c
__device__ float g_h[2 * Hn * Bn];             // ping-pong, [p][c][b]
__device__ unsigned char g_rst[Tn * Bn];       // [t][b], normalized 0/1
__device__ unsigned g_cnt2[NBG * 16];          // per-bg barrier counters (64B apart)
__device__ volatile unsigned g_gen2[NBG * 16];

// ---------------- packed fp32 FMA (Blackwell f32x2) -------------------------
__device__ __forceinline__ float2 ffma2(float2 a, float2 b, float2 c) {
    unsigned long long au = *reinterpret_cast<unsigned long long*>(&a);
    unsigned long long bu = *reinterpret_cast<unsigned long long*>(&b);
    unsigned long long cu = *reinterpret_cast<unsigned long long*>(&c);
    unsigned long long du;
    asm("fma.rn.f32x2 %0, %1, %2, %3;" : "=l"(du) : "l"(au), "l"(bu), "l"(cu));
    return *reinterpret_cast<float2*>(&du);
}
__device__ __forceinline__ float2 add2(float2 a, float2 b) {
    return make_float2(a.x + b.x, a.y + b.y);
}

// ---------------- init ------------------------------------------------------
__global__ void init_kernel(const float* __restrict__ h0,
                            const unsigned char* __restrict__ resets) {
    int i = blockIdx.x * blockDim.x + threadIdx.x;
    if (i < NBG) { g_cnt2[i * 16] = 0; g_gen2[i * 16] = 0; }

    // resets dtype ambiguous (int32 vs bool/u8): int32 0/1 LE has zero bytes
    // at offsets i%4 != 0.
    bool is_u8 = false;
    #pragma unroll 4
    for (int j = 0; j < 64; j++) {
        if (resets[j * 4 + 1] | resets[j * 4 + 2] | resets[j * 4 + 3]) is_u8 = true;
    }

    if (i < Hn * Bn) {
        int c = i / Bn, b = i % Bn;
        g_h[c * Bn + b] = h0[b * Hn + c];   // [c][b] <- [b][c]
    }
    if (i < Tn * Bn) {
        int t = i / Bn, b = i % Bn;
        int src = b * Tn + t;
        unsigned char v;
        if (is_u8) v = resets[src] ? 1 : 0;
        else       v = reinterpret_cast<const int*>(resets)[src] ? 1 : 0;
        g_rst[i] = v;
    }
}

// ---------------- Gi = x @ Wi + bi, stored [t][g][b] ------------------------
// 64(g) x 128(b) tile, 256 threads, 4g x 8b micro-tile, FFMA2 inner loop.
#define BS_LD 132

__global__ void __launch_bounds__(256) gi_gemm(const float* __restrict__ x,
                                               const float* __restrict__ Wi,
                                               const float* __restrict__ bi) {
    int t  = blockIdx.z;
    int g0 = blockIdx.y * 64;
    int b0 = blockIdx.x * 128;

    __shared__ float As[16][64];
    __shared__ float Bs[16 * BS_LD];

    int tid = threadIdx.x;
    int tx = tid & 15;             // -> b octet
    int ty = tid >> 4;             // -> g quad

    float2 acc[4][4];
    #pragma unroll
    for (int i = 0; i < 4; i++)
        #pragma unroll
        for (int j = 0; j < 4; j++) acc[i][j] = make_float2(0.f, 0.f);

    for (int k0 = 0; k0 < Hn; k0 += 16) {
        {
            int gg = tid & 63;
            int kk = tid >> 6;
            #pragma unroll
            for (int r = 0; r < 4; r++)
                As[kk + 4 * r][gg] = Wi[(size_t)(k0 + kk + 4 * r) * G3 + g0 + gg];
        }
        {
            #pragma unroll
            for (int rep = 0; rep < 2; rep++) {
                int idx = tid + rep * 256;
                int bb = idx >> 2;
                int kq = (idx & 3) * 4;
                const float4 v = *reinterpret_cast<const float4*>(
                    &x[((size_t)(b0 + bb) * Tn + t) * Hn + k0 + kq]);
                Bs[(kq + 0) * BS_LD + bb] = v.x;
                Bs[(kq + 1) * BS_LD + bb] = v.y;
                Bs[(kq + 2) * BS_LD + bb] = v.z;
                Bs[(kq + 3) * BS_LD + bb] = v.w;
            }
        }
        __syncthreads();

        #pragma unroll
        for (int kk = 0; kk < 16; kk++) {
            float4 a4 = *reinterpret_cast<const float4*>(&As[kk][ty * 4]);
            float4 bA = *reinterpret_cast<const float4*>(&Bs[kk * BS_LD + tx * 8]);
            float4 bB = *reinterpret_cast<const float4*>(&Bs[kk * BS_LD + tx * 8 + 4]);
            float2 bp[4] = { make_float2(bA.x, bA.y), make_float2(bA.z, bA.w),
                             make_float2(bB.x, bB.y), make_float2(bB.z, bB.w) };
            float av[4] = { a4.x, a4.y, a4.z, a4.w };
            #pragma unroll
            for (int i = 0; i < 4; i++) {
                float2 ai = make_float2(av[i], av[i]);
                #pragma unroll
                for (int j = 0; j < 4; j++)
                    acc[i][j] = ffma2(ai, bp[j], acc[i][j]);
            }
        }
        __syncthreads();
    }

    #pragma unroll
    for (int i = 0; i < 4; i++) {
        int g = g0 + ty * 4 + i;
        float bv = bi[g];
        float4 o0 = make_float4(acc[i][0].x + bv, acc[i][0].y + bv,
                                acc[i][1].x + bv, acc[i][1].y + bv);
        float4 o1 = make_float4(acc[i][2].x + bv, acc[i][2].y + bv,
                                acc[i][3].x + bv, acc[i][3].y + bv);
        float* dst = &g_Gi[((size_t)t * G3 + g) * Bn + b0 + tx * 8];
        *reinterpret_cast<float4*>(dst)     = o0;
        *reinterpret_cast<float4*>(dst + 4) = o1;
    }
}

// ---------------- recurrent scan -------------------------------------------
// Block (bg,cg): batch rows [bg*32, +32), h-cols [cg*16, +16).
// Thread tid = kh*64 + bq*16 + cl:  kh k-half, bq -> 8 batch rows, cl -> 1 col.
__device__ __forceinline__ float sigmoidf_(float v) {
    return __fdividef(1.f, 1.f + __expf(-v));
}

__global__ void __launch_bounds__(RNN_THREADS, 1)
rnn_kernel(const float* __restrict__ Wh, const float* __restrict__ bnb,
           float* __restrict__ out) {
    extern __shared__ char smraw[];
    float4* ws  = reinterpret_cast<float4*>(smraw);                  // [256][16] 64KB
    float*  hs  = reinterpret_cast<float*>(smraw + 65536);           // [256][HS_LD] 40KB
    float2* red = reinterpret_cast<float2*>(smraw + 65536 + Hn * HS_LD * 4); // [64][2][6] 6KB

    const int tid = threadIdx.x;
    const int bg  = blockIdx.x >> 4;
    const int cg  = blockIdx.x & 15;
    const int kh  = tid >> 6;            // 0,1
    const int bq  = (tid >> 4) & 3;      // 0..3
    const int cl  = tid & 15;            // 0..15
    const int cG  = cg * 16 + cl;        // global h-col for this thread
    const int bB  = bg * 32;             // base batch row of block

    // ---- load Wh slice into SMEM, packed {wr, wz, wn, 0} per (k, cl) ----
    for (int idx = tid; idx < Hn * 16; idx += RNN_THREADS) {
        int k = idx >> 4, c = cg * 16 + (idx & 15);
        const float* w = Wh + (size_t)k * G3;
        ws[idx] = make_float4(w[c], w[256 + c], w[512 + c], 0.f);
    }
    const float bnv = bnb[cG];
    __syncthreads();

    float* outy = out + Hn * Bn;                 // ys after hT
    const int bact = bq * 8 + kh * 4;            // 4 batch rows this thread activates
    const int b0g  = bB + bact;

    unsigned* cntp = &g_cnt2[bg * 16];
    volatile unsigned* genp = &g_gen2[bg * 16];

    for (int t = 0; t < Tn; t++) {
        const int p = t & 1;
        const float* hin = g_h + p * (Hn * Bn);

        // ---- stage masked h[32b, 256k] into hs (L2 reads, .cg) ----
        #pragma unroll
        for (int it = 0; it < 16; it++) {
            int fidx = it * RNN_THREADS + tid;   // 0..2047 float4s
            int row  = fidx >> 3;
            int c4   = (fidx & 7) * 4;
            float4 v;
            {
                const float4* src = reinterpret_cast<const float4*>(
                    &hin[row * Bn + bB + c4]);
                v = __ldcg(src);
            }
            uchar4 q = *reinterpret_cast<const uchar4*>(&g_rst[t * Bn + bB + c4]);
            v.x = q.x ? 0.f : v.x;
            v.y = q.y ? 0.f : v.y;
            v.z = q.z ? 0.f : v.z;
            v.w = q.w ? 0.f : v.w;
            *reinterpret_cast<float4*>(&hs[row * HS_LD + c4]) = v;
        }

        // ---- prefetch gi for the 4 rows this thread activates ----
        const float* gi = g_Gi + (size_t)t * G3 * Bn;
        float4 gr = __ldcs(reinterpret_cast<const float4*>(&gi[(      cG) * Bn + b0g]));
        float4 gz = __ldcs(reinterpret_cast<const float4*>(&gi[(256 + cG) * Bn + b0g]));
        float4 gn = __ldcs(reinterpret_cast<const float4*>(&gi[(512 + cG) * Bn + b0g]));

        __syncthreads();

        // ---- k-loop: gh partials over this thread's k-half ----
        float2 ar0 = {0,0}, ar1 = {0,0}, ar2 = {0,0}, ar3 = {0,0};
        float2 az0 = {0,0}, az1 = {0,0}, az2 = {0,0}, az3 = {0,0};
        float2 an0 = {0,0}, an1 = {0,0}, an2 = {0,0}, an3 = {0,0};
        {
            const float4* wp = ws + cl;
            const float*  hp = hs + bq * 8;
            const int kb = kh * 128;
            #pragma unroll 8
            for (int k = 0; k < 128; k++) {
                const int kk = kb + k;
                float4 w  = wp[kk * 16];
                float4 ha = *reinterpret_cast<const float4*>(&hp[kk * HS_LD]);
                float4 hb = *reinterpret_cast<const float4*>(&hp[kk * HS_LD + 4]);
                float2 wr = make_float2(w.x, w.x);
                float2 wz = make_float2(w.y, w.y);
                float2 wn = make_float2(w.z, w.z);
                float2 h0 = make_float2(ha.x, ha.y);
                float2 h1 = make_float2(ha.z, ha.w);
                float2 h2 = make_float2(hb.x, hb.y);
                float2 h3 = make_float2(hb.z, hb.w);
                ar0 = ffma2(wr, h0, ar0); ar1 = ffma2(wr, h1, ar1);
                ar2 = ffma2(wr, h2, ar2); ar3 = ffma2(wr, h3, ar3);
                az0 = ffma2(wz, h0, az0); az1 = ffma2(wz, h1, az1);
                az2 = ffma2(wz, h2, az2); az3 = ffma2(wz, h3, az3);
                an0 = ffma2(wn, h0, an0); an1 = ffma2(wn, h1, an1);
                an2 = ffma2(wn, h2, an2); an3 = ffma2(wn, h3, an3);
            }
        }

        // ---- exchange partner-half partials through SMEM ----
        // thread activates j in [kh*4, kh*4+4); sends accs for partner's range
        {
            float2* slot = red + ((bq * 16 + cl) * 2 + kh) * 6;
            if (kh == 0) {
                slot[0] = ar2; slot[1] = ar3; slot[2] = az2;
                slot[3] = az3; slot[4] = an2; slot[5] = an3;
            } else {
                slot[0] = ar0; slot[1] = ar1; slot[2] = az0;
                slot[3] = az1; slot[4] = an0; slot[5] = an1;
            }
        }
        __syncthreads();
        float2 sr0, sr1, sz0, sz1, sn0, sn1;   // full sums for my 4 rows
        {
            const float2* pslot = red + ((bq * 16 + cl) * 2 + (1 - kh)) * 6;
            if (kh == 0) {
                sr0 = add2(ar0, pslot[0]); sr1 = add2(ar1, pslot[1]);
                sz0 = add2(az0, pslot[2]); sz1 = add2(az1, pslot[3]);
                sn0 = add2(an0, pslot[4]); sn1 = add2(an1, pslot[5]);
            } else {
                sr0 = add2(ar2, pslot[0]); sr1 = add2(ar3, pslot[1]);
                sz0 = add2(az2, pslot[2]); sz1 = add2(az3, pslot[3]);
                sn0 = add2(an2, pslot[4]); sn1 = add2(an3, pslot[5]);
            }
        }

        // ---- activation + h' for 4 rows ----
        float4 hprev = *reinterpret_cast<const float4*>(&hs[cG * HS_LD + bact]);
        float hr[4] = { sr0.x, sr0.y, sr1.x, sr1.y };
        float hz[4] = { sz0.x, sz0.y, sz1.x, sz1.y };
        float hn[4] = { sn0.x, sn0.y, sn1.x, sn1.y };
        float ir[4] = { gr.x, gr.y, gr.z, gr.w };
        float iz[4] = { gz.x, gz.y, gz.z, gz.w };
        float inn[4] = { gn.x, gn.y, gn.z, gn.w };
        float hp4[4] = { hprev.x, hprev.y, hprev.z, hprev.w };
        float nh[4];
        #pragma unroll
        for (int j = 0; j < 4; j++) {
            float r = sigmoidf_(ir[j] + hr[j]);
            float z = sigmoidf_(iz[j] + hz[j]);
            float n = tanhf(inn[j] + r * (hn[j] + bnv));
            nh[j] = (1.f - z) * n + z * hp4[j];
        }

        float* hout = g_h + (p ^ 1) * (Hn * Bn);
        {
            float4 o = make_float4(nh[0], nh[1], nh[2], nh[3]);
            __stcg(reinterpret_cast<float4*>(&hout[cG * Bn + b0g]), o);
        }

        #pragma unroll
        for (int j = 0; j < 4; j++)
            outy[((size_t)(b0g + j) * Tn + t) * Hn + cG] = nh[j];
        if (t == Tn - 1) {
            #pragma unroll
            for (int j = 0; j < 4; j++)
                out[(b0g + j) * Hn + cG] = nh[j];
        }

        // ---- barrier among the 16 blocks of this batch-group ----
        if (t < Tn - 1) {
            __syncthreads();
            if (tid == 0) {
                __threadfence();
                unsigned a = atomicAdd(cntp, 1u);
                if (a == 15u) {
                    *cntp = 0;
                    __threadfence();
                    atomicAdd((unsigned*)genp, 1u);
                } else {
                    unsigned target = (unsigned)(t + 1);
                    while (*genp < target) { __nanosleep(32); }
                }
                __threadfence();
            }
            __syncthreads();
        }
    }
}

// ---------------- launch ----------------------------------------------------
#define RNN_SMEM (65536 + Hn * HS_LD * 4 + 64 * 2 * 6 * 8)

extern "C" void kernel_launch(void* const* d_in, const int* in_sizes, int n_in,
                              void* d_out, int out_size) {
    const float*         x      = (const float*)d_in[0];
    const unsigned char* resets = (const unsigned char*)d_in[1];
    const float*         Wi     = (const float*)d_in[2];
    const float*         bi     = (const float*)d_in[3];
    const float*         Wh     = (const float*)d_in[4];
    const float*         bn     = (const float*)d_in[5];
    const float*         h0     = (const float*)d_in[6];
    float* out = (float*)d_out;

    cudaFuncSetAttribute(rnn_kernel, cudaFuncAttributeMaxDynamicSharedMemorySize,
                         RNN_SMEM);

    init_kernel<<<(Tn * Bn + 255) / 256, 256>>>(h0, resets);

    dim3 g(Bn / 128, G3 / 64, Tn);
    gi_gemm<<<g, 256>>>(x, Wi, bi);

    rnn_kernel<<<RNN_BLOCKS, RNN_THREADS, RNN_SMEM>>>(Wh, bn, out);
}